// round 1
// baseline (speedup 1.0000x reference)
#include <cuda_runtime.h>

#define N_TOK 4096
#define DIN   512
#define DOUT  512
#define PNUM  8
#define KNUM  8
#define QDIM  (DIN * KNUM)   // 4096

// ---- scratch (static device globals; allowed) ----
__device__ float g_phi[N_TOK * QDIM];          // 64 MB  softplus(x + shift) features
__device__ float g_wphi[DOUT * QDIM];          // 8 MB   softplus(phi_raw)^2
__device__ float g_xproj[N_TOK * DOUT];        // 8 MB   phi @ wphi^T + bias
__device__ float g_z0[PNUM * N_TOK * DOUT];    // 64 MB  sp(xproj * g1[p])
__device__ float g_w2[PNUM * DOUT * DOUT];     // 8 MB   softplus(raw_weight2)^2
__device__ float g_zw[PNUM * DIN * DOUT];      // 8 MB   z_weight[:, :512] + z_weight[:, 512:]

__device__ __forceinline__ float sp_f(float v) {
    // numerically robust softplus, matches jax.nn.softplus to fp32 ulp-level
    return fmaxf(v, 0.0f) + log1pf(expf(-fabsf(v)));
}
__device__ __forceinline__ float sig_f(float v) {
    return 1.0f / (1.0f + expf(-v));
}

// ---------------------------------------------------------------------------
// prep: transform all weights. 2,097,152 threads; all three arrays same size.
// ---------------------------------------------------------------------------
__global__ void prep_kernel(const float* __restrict__ phi_raw,
                            const float* __restrict__ rw2,
                            const float* __restrict__ zw) {
    int idx = blockIdx.x * 256 + threadIdx.x;
    if (idx >= DOUT * QDIM) return;  // 2097152 == PNUM*DOUT*DOUT == PNUM*DIN*DOUT
    float s1 = sp_f(phi_raw[idx]);
    g_wphi[idx] = s1 * s1;
    float s2 = sp_f(rw2[idx]);
    g_w2[idx] = s2 * s2;
    int p = idx >> 18;               // idx / (512*512)
    // z_weight is [P, 2*DIN, DOUT]; fold concat([x,x]) into summed weight
    int base = idx + (p << 18);      // p*524288 + c*512 + e
    g_zw[idx] = zw[base] + zw[base + DIN * DOUT];
}

// ---------------------------------------------------------------------------
// phi: materialize softplus(x + shift_k), 8 consecutive features per x elem
// ---------------------------------------------------------------------------
__global__ void phi_kernel(const float* __restrict__ x) {
    int idx = blockIdx.x * 256 + threadIdx.x;   // over N_TOK*DIN = 2097152
    if (idx >= N_TOK * DIN) return;
    float v = x[idx];
    const float step = 2.0f / 7.0f;
    float4 lo = make_float4(sp_f(v - 1.0f),
                            sp_f(v - 1.0f + step),
                            sp_f(v - 1.0f + 2.0f * step),
                            sp_f(v - 1.0f + 3.0f * step));
    float4 hi = make_float4(sp_f(v - 1.0f + 4.0f * step),
                            sp_f(v - 1.0f + 5.0f * step),
                            sp_f(v - 1.0f + 6.0f * step),
                            sp_f(v + 1.0f));
    float4* dst = reinterpret_cast<float4*>(&g_phi[(size_t)idx * 8]);
    dst[0] = lo;
    dst[1] = hi;
}

// ---------------------------------------------------------------------------
// GEMM A: xproj[n,d] = sum_q phi[n,q] * wphi[d,q] + phi_bias[d]
// 64x64 tile, KT=16, 256 threads, 4x4 microtile, k-major smem tiles.
// ---------------------------------------------------------------------------
__global__ __launch_bounds__(256) void gemmA_kernel(const float* __restrict__ phi_bias) {
    __shared__ float As[16][68];   // [k][n]  (68 keeps float4 alignment, spreads banks)
    __shared__ float Bs[16][68];   // [k][d]
    const int n0 = blockIdx.y * 64;
    const int d0 = blockIdx.x * 64;
    const int tid = threadIdx.x;
    const int tx = tid & 15, ty = tid >> 4;
    const int lr = tid >> 2, lk = (tid & 3) * 4;

    float acc[4][4] = {};
    const float* aptr = &g_phi[(size_t)(n0 + lr) * QDIM + lk];
    const float* bptr = &g_wphi[(size_t)(d0 + lr) * QDIM + lk];

    for (int q0 = 0; q0 < QDIM; q0 += 16) {
        float4 a = *reinterpret_cast<const float4*>(aptr + q0);
        float4 b = *reinterpret_cast<const float4*>(bptr + q0);
        __syncthreads();
        As[lk + 0][lr] = a.x; As[lk + 1][lr] = a.y; As[lk + 2][lr] = a.z; As[lk + 3][lr] = a.w;
        Bs[lk + 0][lr] = b.x; Bs[lk + 1][lr] = b.y; Bs[lk + 2][lr] = b.z; Bs[lk + 3][lr] = b.w;
        __syncthreads();
#pragma unroll
        for (int kk = 0; kk < 16; kk++) {
            float4 av = *reinterpret_cast<const float4*>(&As[kk][ty * 4]);
            float4 bv = *reinterpret_cast<const float4*>(&Bs[kk][tx * 4]);
            float ar[4] = {av.x, av.y, av.z, av.w};
            float bc[4] = {bv.x, bv.y, bv.z, bv.w};
#pragma unroll
            for (int r = 0; r < 4; r++)
#pragma unroll
                for (int c = 0; c < 4; c++)
                    acc[r][c] = fmaf(ar[r], bc[c], acc[r][c]);
        }
    }

    float4 bias = *reinterpret_cast<const float4*>(&phi_bias[d0 + tx * 4]);
    float bb[4] = {bias.x, bias.y, bias.z, bias.w};
#pragma unroll
    for (int r = 0; r < 4; r++) {
        float4 o = make_float4(acc[r][0] + bb[0], acc[r][1] + bb[1],
                               acc[r][2] + bb[2], acc[r][3] + bb[3]);
        *reinterpret_cast<float4*>(&g_xproj[(size_t)(n0 + ty * 4 + r) * DOUT + d0 + tx * 4]) = o;
    }
}

// ---------------------------------------------------------------------------
// z0: sp(xproj * sigmoid(gate_raw[p])) materialized per expert (avoids 8x
// softplus recompute in stage B)
// ---------------------------------------------------------------------------
__global__ void z0_kernel(const float* __restrict__ gate_raw) {
    int idx4 = blockIdx.x * 256 + threadIdx.x;   // over 16777216/4 = 4194304
    if (idx4 >= (PNUM * N_TOK * DOUT) / 4) return;
    int p = idx4 >> 19;                          // / (N_TOK*DOUT/4)
    float g1 = sig_f(gate_raw[p]);
    int off = (idx4 & 524287) * 4;               // within-expert = xproj offset
    float4 v = *reinterpret_cast<const float4*>(&g_xproj[off]);
    float4 o = make_float4(sp_f(v.x * g1), sp_f(v.y * g1),
                           sp_f(v.z * g1), sp_f(v.w * g1));
    *reinterpret_cast<float4*>(&g_z0[(size_t)idx4 * 4]) = o;
}

// ---------------------------------------------------------------------------
// Stage B: per expert p, dual GEMM with fused nonlinear epilogue.
//   acc1[n,e] = z0_p[n,:] . w2_p[e,:]        (NT)
//   acc2[n,e] = x[n,:]    . zw_p[:,e]        (NN; zw already k-major rows)
//   out[n,p,e] = sp( sp((acc1+bias2)*g2) + acc2 ) + obias
// ---------------------------------------------------------------------------
__global__ __launch_bounds__(256) void stageB_kernel(const float* __restrict__ x,
                                                     const float* __restrict__ bias2,
                                                     const float* __restrict__ gate_raw2,
                                                     const float* __restrict__ obias,
                                                     float* __restrict__ out) {
    __shared__ float As1[16][68];  // z0 tile  [k][n]
    __shared__ float Bs1[16][68];  // w2 tile  [k][e]
    __shared__ float As2[16][68];  // x tile   [k][n]
    __shared__ float Bs2[16][68];  // zw tile  [k][e]
    const int p = blockIdx.z;
    const int n0 = blockIdx.y * 64;
    const int e0 = blockIdx.x * 64;
    const int tid = threadIdx.x;
    const int tx = tid & 15, ty = tid >> 4;
    const int lr = tid >> 2, lk = (tid & 3) * 4;
    const int br = tid >> 4, bc = (tid & 15) * 4;

    float acc1[4][4] = {}, acc2[4][4] = {};

    const float* z0p = &g_z0[(size_t)p * (N_TOK * DOUT) + (size_t)(n0 + lr) * DOUT + lk];
    const float* w2p = &g_w2[(size_t)p * (DOUT * DOUT) + (size_t)(e0 + lr) * DOUT + lk];
    const float* xp  = &x[(size_t)(n0 + lr) * DIN + lk];
    const float* zwp = &g_zw[(size_t)p * (DIN * DOUT) + (size_t)br * DOUT + e0 + bc];

    for (int k0 = 0; k0 < DOUT; k0 += 16) {
        float4 a1 = *reinterpret_cast<const float4*>(z0p + k0);
        float4 b1 = *reinterpret_cast<const float4*>(w2p + k0);
        float4 a2 = *reinterpret_cast<const float4*>(xp + k0);
        float4 b2 = *reinterpret_cast<const float4*>(zwp + (size_t)k0 * DOUT);
        __syncthreads();
        As1[lk + 0][lr] = a1.x; As1[lk + 1][lr] = a1.y; As1[lk + 2][lr] = a1.z; As1[lk + 3][lr] = a1.w;
        Bs1[lk + 0][lr] = b1.x; Bs1[lk + 1][lr] = b1.y; Bs1[lk + 2][lr] = b1.z; Bs1[lk + 3][lr] = b1.w;
        As2[lk + 0][lr] = a2.x; As2[lk + 1][lr] = a2.y; As2[lk + 2][lr] = a2.z; As2[lk + 3][lr] = a2.w;
        *reinterpret_cast<float4*>(&Bs2[br][bc]) = b2;
        __syncthreads();
#pragma unroll
        for (int kk = 0; kk < 16; kk++) {
            float4 a1v = *reinterpret_cast<const float4*>(&As1[kk][ty * 4]);
            float4 b1v = *reinterpret_cast<const float4*>(&Bs1[kk][tx * 4]);
            float4 a2v = *reinterpret_cast<const float4*>(&As2[kk][ty * 4]);
            float4 b2v = *reinterpret_cast<const float4*>(&Bs2[kk][tx * 4]);
            float a1r[4] = {a1v.x, a1v.y, a1v.z, a1v.w};
            float b1c[4] = {b1v.x, b1v.y, b1v.z, b1v.w};
            float a2r[4] = {a2v.x, a2v.y, a2v.z, a2v.w};
            float b2c[4] = {b2v.x, b2v.y, b2v.z, b2v.w};
#pragma unroll
            for (int r = 0; r < 4; r++)
#pragma unroll
                for (int c = 0; c < 4; c++) {
                    acc1[r][c] = fmaf(a1r[r], b1c[c], acc1[r][c]);
                    acc2[r][c] = fmaf(a2r[r], b2c[c], acc2[r][c]);
                }
        }
    }

    float g2 = sig_f(gate_raw2[p]);
    float4 bv = *reinterpret_cast<const float4*>(&bias2[p * DOUT + e0 + tx * 4]);
    float4 ov = *reinterpret_cast<const float4*>(&obias[p * DOUT + e0 + tx * 4]);
    float bb[4] = {bv.x, bv.y, bv.z, bv.w};
    float ob[4] = {ov.x, ov.y, ov.z, ov.w};
#pragma unroll
    for (int r = 0; r < 4; r++) {
        float o_[4];
#pragma unroll
        for (int c = 0; c < 4; c++) {
            float z1 = sp_f((acc1[r][c] + bb[c]) * g2);
            o_[c] = sp_f(z1 + acc2[r][c]) + ob[c];
        }
        int row = n0 + ty * 4 + r;
        *reinterpret_cast<float4*>(&out[(size_t)row * (PNUM * DOUT) + p * DOUT + e0 + tx * 4]) =
            make_float4(o_[0], o_[1], o_[2], o_[3]);
    }
}

// ---------------------------------------------------------------------------
extern "C" void kernel_launch(void* const* d_in, const int* in_sizes, int n_in,
                              void* d_out, int out_size) {
    const float* x        = (const float*)d_in[0];  // [2,2048,512]
    const float* phi_raw  = (const float*)d_in[1];  // [512,4096]
    const float* phi_bias = (const float*)d_in[2];  // [512]
    const float* rw2      = (const float*)d_in[3];  // [8,512,512]
    const float* bias2    = (const float*)d_in[4];  // [8,512]
    const float* graw2    = (const float*)d_in[5];  // [8]
    const float* zw       = (const float*)d_in[6];  // [8,1024,512]
    const float* graw     = (const float*)d_in[7];  // [8]
    const float* obias    = (const float*)d_in[8];  // [8,512]
    float* out = (float*)d_out;                     // [4096,8,512]

    prep_kernel<<<8192, 256>>>(phi_raw, rw2, zw);
    phi_kernel<<<8192, 256>>>(x);
    gemmA_kernel<<<dim3(8, 64), 256>>>(phi_bias);
    z0_kernel<<<16384, 256>>>(graw);
    stageB_kernel<<<dim3(8, 64, 8), 256>>>(x, bias2, graw2, obias, out);
}

// round 2
// speedup vs baseline: 1.0000x; 1.0000x over previous
#include <cuda_runtime.h>

#define N_TOK 4096
#define DIN   512
#define DOUT  512
#define PNUM  8
#define KNUM  8
#define QDIM  (DIN * KNUM)   // 4096

// ---- scratch (static device globals; allowed) ----
__device__ float g_phi[N_TOK * QDIM];          // 64 MB  softplus(x + shift) features
__device__ float g_wphi[DOUT * QDIM];          // 8 MB   softplus(phi_raw)^2
__device__ float g_xproj[N_TOK * DOUT];        // 8 MB   phi @ wphi^T + bias
__device__ float g_z0[PNUM * N_TOK * DOUT];    // 64 MB  sp(xproj * g1[p])
__device__ float g_w2[PNUM * DOUT * DOUT];     // 8 MB   softplus(raw_weight2)^2
__device__ float g_zw[PNUM * DIN * DOUT];      // 8 MB   z_weight[:, :512] + z_weight[:, 512:]

__device__ __forceinline__ float sp_f(float v) {
    // numerically robust softplus, matches jax.nn.softplus to fp32 ulp-level
    return fmaxf(v, 0.0f) + log1pf(expf(-fabsf(v)));
}
__device__ __forceinline__ float sig_f(float v) {
    return 1.0f / (1.0f + expf(-v));
}

// ---------------------------------------------------------------------------
// prep: transform all weights. 2,097,152 threads; all three arrays same size.
// ---------------------------------------------------------------------------
__global__ void prep_kernel(const float* __restrict__ phi_raw,
                            const float* __restrict__ rw2,
                            const float* __restrict__ zw) {
    int idx = blockIdx.x * 256 + threadIdx.x;
    if (idx >= DOUT * QDIM) return;  // 2097152 == PNUM*DOUT*DOUT == PNUM*DIN*DOUT
    float s1 = sp_f(phi_raw[idx]);
    g_wphi[idx] = s1 * s1;
    float s2 = sp_f(rw2[idx]);
    g_w2[idx] = s2 * s2;
    int p = idx >> 18;               // idx / (512*512)
    // z_weight is [P, 2*DIN, DOUT]; fold concat([x,x]) into summed weight
    int base = idx + (p << 18);      // p*524288 + c*512 + e
    g_zw[idx] = zw[base] + zw[base + DIN * DOUT];
}

// ---------------------------------------------------------------------------
// phi: materialize softplus(x + shift_k), 8 consecutive features per x elem
// ---------------------------------------------------------------------------
__global__ void phi_kernel(const float* __restrict__ x) {
    int idx = blockIdx.x * 256 + threadIdx.x;   // over N_TOK*DIN = 2097152
    if (idx >= N_TOK * DIN) return;
    float v = x[idx];
    const float step = 2.0f / 7.0f;
    float4 lo = make_float4(sp_f(v - 1.0f),
                            sp_f(v - 1.0f + step),
                            sp_f(v - 1.0f + 2.0f * step),
                            sp_f(v - 1.0f + 3.0f * step));
    float4 hi = make_float4(sp_f(v - 1.0f + 4.0f * step),
                            sp_f(v - 1.0f + 5.0f * step),
                            sp_f(v - 1.0f + 6.0f * step),
                            sp_f(v + 1.0f));
    float4* dst = reinterpret_cast<float4*>(&g_phi[(size_t)idx * 8]);
    dst[0] = lo;
    dst[1] = hi;
}

// ---------------------------------------------------------------------------
// GEMM A: xproj[n,d] = sum_q phi[n,q] * wphi[d,q] + phi_bias[d]
// 64x64 tile, KT=16, 256 threads, 4x4 microtile, k-major smem tiles.
// ---------------------------------------------------------------------------
__global__ __launch_bounds__(256) void gemmA_kernel(const float* __restrict__ phi_bias) {
    __shared__ float As[16][68];   // [k][n]  (68 keeps float4 alignment, spreads banks)
    __shared__ float Bs[16][68];   // [k][d]
    const int n0 = blockIdx.y * 64;
    const int d0 = blockIdx.x * 64;
    const int tid = threadIdx.x;
    const int tx = tid & 15, ty = tid >> 4;
    const int lr = tid >> 2, lk = (tid & 3) * 4;

    float acc[4][4] = {};
    const float* aptr = &g_phi[(size_t)(n0 + lr) * QDIM + lk];
    const float* bptr = &g_wphi[(size_t)(d0 + lr) * QDIM + lk];

    for (int q0 = 0; q0 < QDIM; q0 += 16) {
        float4 a = *reinterpret_cast<const float4*>(aptr + q0);
        float4 b = *reinterpret_cast<const float4*>(bptr + q0);
        __syncthreads();
        As[lk + 0][lr] = a.x; As[lk + 1][lr] = a.y; As[lk + 2][lr] = a.z; As[lk + 3][lr] = a.w;
        Bs[lk + 0][lr] = b.x; Bs[lk + 1][lr] = b.y; Bs[lk + 2][lr] = b.z; Bs[lk + 3][lr] = b.w;
        __syncthreads();
#pragma unroll
        for (int kk = 0; kk < 16; kk++) {
            float4 av = *reinterpret_cast<const float4*>(&As[kk][ty * 4]);
            float4 bv = *reinterpret_cast<const float4*>(&Bs[kk][tx * 4]);
            float ar[4] = {av.x, av.y, av.z, av.w};
            float bc[4] = {bv.x, bv.y, bv.z, bv.w};
#pragma unroll
            for (int r = 0; r < 4; r++)
#pragma unroll
                for (int c = 0; c < 4; c++)
                    acc[r][c] = fmaf(ar[r], bc[c], acc[r][c]);
        }
    }

    float4 bias = *reinterpret_cast<const float4*>(&phi_bias[d0 + tx * 4]);
    float bb[4] = {bias.x, bias.y, bias.z, bias.w};
#pragma unroll
    for (int r = 0; r < 4; r++) {
        float4 o = make_float4(acc[r][0] + bb[0], acc[r][1] + bb[1],
                               acc[r][2] + bb[2], acc[r][3] + bb[3]);
        *reinterpret_cast<float4*>(&g_xproj[(size_t)(n0 + ty * 4 + r) * DOUT + d0 + tx * 4]) = o;
    }
}

// ---------------------------------------------------------------------------
// z0: sp(xproj * sigmoid(gate_raw[p])) materialized per expert (avoids 8x
// softplus recompute in stage B)
// ---------------------------------------------------------------------------
__global__ void z0_kernel(const float* __restrict__ gate_raw) {
    int idx4 = blockIdx.x * 256 + threadIdx.x;   // over 16777216/4 = 4194304
    if (idx4 >= (PNUM * N_TOK * DOUT) / 4) return;
    int p = idx4 >> 19;                          // / (N_TOK*DOUT/4)
    float g1 = sig_f(gate_raw[p]);
    int off = (idx4 & 524287) * 4;               // within-expert = xproj offset
    float4 v = *reinterpret_cast<const float4*>(&g_xproj[off]);
    float4 o = make_float4(sp_f(v.x * g1), sp_f(v.y * g1),
                           sp_f(v.z * g1), sp_f(v.w * g1));
    *reinterpret_cast<float4*>(&g_z0[(size_t)idx4 * 4]) = o;
}

// ---------------------------------------------------------------------------
// Stage B: per expert p, dual GEMM with fused nonlinear epilogue.
//   acc1[n,e] = z0_p[n,:] . w2_p[e,:]        (NT)
//   acc2[n,e] = x[n,:]    . zw_p[:,e]        (NN; zw already k-major rows)
//   out[n,p,e] = sp( sp((acc1+bias2)*g2) + acc2 ) + obias
// ---------------------------------------------------------------------------
__global__ __launch_bounds__(256) void stageB_kernel(const float* __restrict__ x,
                                                     const float* __restrict__ bias2,
                                                     const float* __restrict__ gate_raw2,
                                                     const float* __restrict__ obias,
                                                     float* __restrict__ out) {
    __shared__ float As1[16][68];  // z0 tile  [k][n]
    __shared__ float Bs1[16][68];  // w2 tile  [k][e]
    __shared__ float As2[16][68];  // x tile   [k][n]
    __shared__ float Bs2[16][68];  // zw tile  [k][e]
    const int p = blockIdx.z;
    const int n0 = blockIdx.y * 64;
    const int e0 = blockIdx.x * 64;
    const int tid = threadIdx.x;
    const int tx = tid & 15, ty = tid >> 4;
    const int lr = tid >> 2, lk = (tid & 3) * 4;
    const int br = tid >> 4, bc = (tid & 15) * 4;

    float acc1[4][4] = {}, acc2[4][4] = {};

    const float* z0p = &g_z0[(size_t)p * (N_TOK * DOUT) + (size_t)(n0 + lr) * DOUT + lk];
    const float* w2p = &g_w2[(size_t)p * (DOUT * DOUT) + (size_t)(e0 + lr) * DOUT + lk];
    const float* xp  = &x[(size_t)(n0 + lr) * DIN + lk];
    const float* zwp = &g_zw[(size_t)p * (DIN * DOUT) + (size_t)br * DOUT + e0 + bc];

    for (int k0 = 0; k0 < DOUT; k0 += 16) {
        float4 a1 = *reinterpret_cast<const float4*>(z0p + k0);
        float4 b1 = *reinterpret_cast<const float4*>(w2p + k0);
        float4 a2 = *reinterpret_cast<const float4*>(xp + k0);
        float4 b2 = *reinterpret_cast<const float4*>(zwp + (size_t)k0 * DOUT);
        __syncthreads();
        As1[lk + 0][lr] = a1.x; As1[lk + 1][lr] = a1.y; As1[lk + 2][lr] = a1.z; As1[lk + 3][lr] = a1.w;
        Bs1[lk + 0][lr] = b1.x; Bs1[lk + 1][lr] = b1.y; Bs1[lk + 2][lr] = b1.z; Bs1[lk + 3][lr] = b1.w;
        As2[lk + 0][lr] = a2.x; As2[lk + 1][lr] = a2.y; As2[lk + 2][lr] = a2.z; As2[lk + 3][lr] = a2.w;
        *reinterpret_cast<float4*>(&Bs2[br][bc]) = b2;
        __syncthreads();
#pragma unroll
        for (int kk = 0; kk < 16; kk++) {
            float4 a1v = *reinterpret_cast<const float4*>(&As1[kk][ty * 4]);
            float4 b1v = *reinterpret_cast<const float4*>(&Bs1[kk][tx * 4]);
            float4 a2v = *reinterpret_cast<const float4*>(&As2[kk][ty * 4]);
            float4 b2v = *reinterpret_cast<const float4*>(&Bs2[kk][tx * 4]);
            float a1r[4] = {a1v.x, a1v.y, a1v.z, a1v.w};
            float b1c[4] = {b1v.x, b1v.y, b1v.z, b1v.w};
            float a2r[4] = {a2v.x, a2v.y, a2v.z, a2v.w};
            float b2c[4] = {b2v.x, b2v.y, b2v.z, b2v.w};
#pragma unroll
            for (int r = 0; r < 4; r++)
#pragma unroll
                for (int c = 0; c < 4; c++) {
                    acc1[r][c] = fmaf(a1r[r], b1c[c], acc1[r][c]);
                    acc2[r][c] = fmaf(a2r[r], b2c[c], acc2[r][c]);
                }
        }
    }

    float g2 = sig_f(gate_raw2[p]);
    float4 bv = *reinterpret_cast<const float4*>(&bias2[p * DOUT + e0 + tx * 4]);
    float4 ov = *reinterpret_cast<const float4*>(&obias[p * DOUT + e0 + tx * 4]);
    float bb[4] = {bv.x, bv.y, bv.z, bv.w};
    float ob[4] = {ov.x, ov.y, ov.z, ov.w};
#pragma unroll
    for (int r = 0; r < 4; r++) {
        float o_[4];
#pragma unroll
        for (int c = 0; c < 4; c++) {
            float z1 = sp_f((acc1[r][c] + bb[c]) * g2);
            o_[c] = sp_f(z1 + acc2[r][c]) + ob[c];
        }
        int row = n0 + ty * 4 + r;
        *reinterpret_cast<float4*>(&out[(size_t)row * (PNUM * DOUT) + p * DOUT + e0 + tx * 4]) =
            make_float4(o_[0], o_[1], o_[2], o_[3]);
    }
}

// ---------------------------------------------------------------------------
extern "C" void kernel_launch(void* const* d_in, const int* in_sizes, int n_in,
                              void* d_out, int out_size) {
    const float* x        = (const float*)d_in[0];  // [2,2048,512]
    const float* phi_raw  = (const float*)d_in[1];  // [512,4096]
    const float* phi_bias = (const float*)d_in[2];  // [512]
    const float* rw2      = (const float*)d_in[3];  // [8,512,512]
    const float* bias2    = (const float*)d_in[4];  // [8,512]
    const float* graw2    = (const float*)d_in[5];  // [8]
    const float* zw       = (const float*)d_in[6];  // [8,1024,512]
    const float* graw     = (const float*)d_in[7];  // [8]
    const float* obias    = (const float*)d_in[8];  // [8,512]
    float* out = (float*)d_out;                     // [4096,8,512]

    prep_kernel<<<8192, 256>>>(phi_raw, rw2, zw);
    phi_kernel<<<8192, 256>>>(x);
    gemmA_kernel<<<dim3(8, 64), 256>>>(phi_bias);
    z0_kernel<<<16384, 256>>>(graw);
    stageB_kernel<<<dim3(8, 64, 8), 256>>>(x, bias2, graw2, obias, out);
}

// round 4
// speedup vs baseline: 2.6537x; 2.6536x over previous
#include <cuda_runtime.h>
#include <cuda_bf16.h>
#include <cstdint>

#define N_TOK 4096
#define DIN   512
#define DOUT  512
#define PNUM  8
#define QDIM  4096

// GEMM tiling: 128x128 CTA tile, BK=32, 8 warps (2x4), warp tile 64x32.
#define TILE_B   10240              // 128 rows * 80 bytes (40 bf16, padded)
#define BUF_B    (4 * TILE_B)       // Ah, Al, Bh, Bl
#define GEMM_SMEM (2 * BUF_B)       // 81920

// ---------------- scratch (static device globals) ----------------
__device__ __align__(128) __nv_bfloat16 g_phi_h[N_TOK * QDIM];
__device__ __align__(128) __nv_bfloat16 g_phi_l[N_TOK * QDIM];
__device__ __align__(128) __nv_bfloat16 g_wphi_h[DOUT * QDIM];
__device__ __align__(128) __nv_bfloat16 g_wphi_l[DOUT * QDIM];
__device__ __align__(128) __nv_bfloat16 g_x_h[N_TOK * DIN];
__device__ __align__(128) __nv_bfloat16 g_x_l[N_TOK * DIN];
__device__ __align__(128) __nv_bfloat16 g_w2_h[PNUM * DOUT * DOUT];
__device__ __align__(128) __nv_bfloat16 g_w2_l[PNUM * DOUT * DOUT];
__device__ __align__(128) __nv_bfloat16 g_zwT_h[PNUM * DIN * DOUT];
__device__ __align__(128) __nv_bfloat16 g_zwT_l[PNUM * DIN * DOUT];
__device__ __align__(128) __nv_bfloat16 g_z0_h[PNUM * N_TOK * DOUT];
__device__ __align__(128) __nv_bfloat16 g_z0_l[PNUM * N_TOK * DOUT];
__device__ __align__(128) float g_xproj[N_TOK * DOUT];
__device__ __align__(128) float g_acc2[PNUM * N_TOK * DOUT];

// ---------------- helpers ----------------
__device__ __forceinline__ float sp_f(float v) {
    return fmaxf(v, 0.0f) + log1pf(expf(-fabsf(v)));
}
__device__ __forceinline__ float sig_f(float v) { return 1.0f / (1.0f + expf(-v)); }

__device__ __forceinline__ void split_bf16(float v, __nv_bfloat16& h, __nv_bfloat16& l) {
    h = __float2bfloat16_rn(v);
    l = __float2bfloat16_rn(v - __bfloat162float(h));
}

__device__ __forceinline__ uint32_t smem_u32(const void* p) {
    uint32_t a;
    asm("{ .reg .u64 t; cvta.to.shared.u64 t, %1; cvt.u32.u64 %0, t; }" : "=r"(a) : "l"(p));
    return a;
}

__device__ __forceinline__ void cp16(uint32_t saddr, const void* g) {
    asm volatile("cp.async.cg.shared.global [%0], [%1], 16;" :: "r"(saddr), "l"(g));
}

__device__ __forceinline__ void ldsm4(uint32_t* r, uint32_t addr) {
    asm volatile("ldmatrix.sync.aligned.m8n8.x4.shared.b16 {%0,%1,%2,%3}, [%4];"
                 : "=r"(r[0]), "=r"(r[1]), "=r"(r[2]), "=r"(r[3]) : "r"(addr));
}

__device__ __forceinline__ void mma16816(float* c, const uint32_t* a, const uint32_t* b) {
    asm volatile(
        "mma.sync.aligned.m16n8k16.row.col.f32.bf16.bf16.f32 "
        "{%0,%1,%2,%3}, {%4,%5,%6,%7}, {%8,%9}, {%0,%1,%2,%3};"
        : "+f"(c[0]), "+f"(c[1]), "+f"(c[2]), "+f"(c[3])
        : "r"(a[0]), "r"(a[1]), "r"(a[2]), "r"(a[3]), "r"(b[0]), "r"(b[1]));
}

// ---------------- elementwise kernels ----------------
__global__ void prep_kernel(const float* __restrict__ phi_raw,
                            const float* __restrict__ rw2,
                            const float* __restrict__ zw) {
    int idx = blockIdx.x * 256 + threadIdx.x;
    if (idx >= DOUT * QDIM) return;  // 2097152
    float s1 = sp_f(phi_raw[idx]);
    split_bf16(s1 * s1, g_wphi_h[idx], g_wphi_l[idx]);
    float s2 = sp_f(rw2[idx]);
    split_bf16(s2 * s2, g_w2_h[idx], g_w2_l[idx]);
    // zwT[p][e][c] = zw[p][c][e] + zw[p][c+512][e]  (transpose to k-major NT form)
    int p = idx >> 18;
    int rem = idx & 262143;
    int e = rem >> 9, c = rem & 511;
    int src = p * (2 * DIN * DOUT) + c * DOUT + e;
    float v = zw[src] + zw[src + DIN * DOUT];
    split_bf16(v, g_zwT_h[idx], g_zwT_l[idx]);
}

__global__ void phi_kernel(const float* __restrict__ x) {
    int idx = blockIdx.x * 256 + threadIdx.x;  // N_TOK*DIN
    if (idx >= N_TOK * DIN) return;
    float v = x[idx];
    split_bf16(v, g_x_h[idx], g_x_l[idx]);
    const float step = 2.0f / 7.0f;
    __nv_bfloat16 h8[8], l8[8];
#pragma unroll
    for (int k = 0; k < 8; k++) {
        float f = sp_f(v - 1.0f + step * (float)k);
        split_bf16(f, h8[k], l8[k]);
    }
    *reinterpret_cast<uint4*>(&g_phi_h[(size_t)idx * 8]) = *reinterpret_cast<uint4*>(h8);
    *reinterpret_cast<uint4*>(&g_phi_l[(size_t)idx * 8]) = *reinterpret_cast<uint4*>(l8);
}

__global__ void z0_kernel(const float* __restrict__ gate_raw) {
    int idx4 = blockIdx.x * 256 + threadIdx.x;  // 4194304
    if (idx4 >= (PNUM * N_TOK * DOUT) / 4) return;
    int p = idx4 >> 19;
    float g1 = sig_f(gate_raw[p]);
    int off4 = idx4 & 524287;
    float4 v = *reinterpret_cast<const float4*>(&g_xproj[(size_t)off4 * 4]);
    __nv_bfloat16 h4[4], l4[4];
    split_bf16(sp_f(v.x * g1), h4[0], l4[0]);
    split_bf16(sp_f(v.y * g1), h4[1], l4[1]);
    split_bf16(sp_f(v.z * g1), h4[2], l4[2]);
    split_bf16(sp_f(v.w * g1), h4[3], l4[3]);
    *reinterpret_cast<uint2*>(&g_z0_h[(size_t)idx4 * 4]) = *reinterpret_cast<uint2*>(h4);
    *reinterpret_cast<uint2*>(&g_z0_l[(size_t)idx4 * 4]) = *reinterpret_cast<uint2*>(l4);
}

// ---------------- mma.sync GEMM core ----------------
// C[128x128] = Ah*Bh^T + Ah*Bl^T + Al*Bh^T ; A [M,K] k-major, B [N,K] k-major.
// Both operands padded-smem (80B row stride) double-buffered via cp.async.

__device__ __forceinline__ void compute_chunk(uint32_t abase_h, uint32_t abase_l,
                                              uint32_t bbase_h, uint32_t bbase_l,
                                              uint32_t arow_off, uint32_t brow_off,
                                              float (*acc)[4]) {
#pragma unroll
    for (int ks = 0; ks < 2; ks++) {
        uint32_t ah[4][4], al[4][4], bh[2][4], bl[2][4];
#pragma unroll
        for (int mi = 0; mi < 4; mi++) {
            ldsm4(ah[mi], abase_h + arow_off + mi * 1280 + ks * 32);
            ldsm4(al[mi], abase_l + arow_off + mi * 1280 + ks * 32);
        }
#pragma unroll
        for (int pr = 0; pr < 2; pr++) {
            ldsm4(bh[pr], bbase_h + brow_off + pr * 1280 + ks * 32);
            ldsm4(bl[pr], bbase_l + brow_off + pr * 1280 + ks * 32);
        }
#pragma unroll
        for (int mi = 0; mi < 4; mi++)
#pragma unroll
            for (int ni = 0; ni < 4; ni++) {
                const uint32_t* bhf = &bh[ni >> 1][(ni & 1) * 2];
                const uint32_t* blf = &bl[ni >> 1][(ni & 1) * 2];
                mma16816(acc[mi * 4 + ni], ah[mi], bhf);
                mma16816(acc[mi * 4 + ni], ah[mi], blf);
                mma16816(acc[mi * 4 + ni], al[mi], bhf);
            }
    }
}

template <typename Epi>
__device__ void gemm_core(const __nv_bfloat16* __restrict__ Ah,
                          const __nv_bfloat16* __restrict__ Al,
                          const __nv_bfloat16* __restrict__ Bh,
                          const __nv_bfloat16* __restrict__ Bl,
                          int ldk, int K, int m0, int n0, Epi epi) {
    extern __shared__ char smem[];
    uint32_t sb = smem_u32(smem);
    const int tid = threadIdx.x, lane = tid & 31, wid = tid >> 5;
    const int wm = wid & 1, wn = wid >> 1;

    const __nv_bfloat16* srcs[4] = {Ah + (size_t)m0 * ldk, Al + (size_t)m0 * ldk,
                                    Bh + (size_t)n0 * ldk, Bl + (size_t)n0 * ldk};
    const int cb = tid & 3;

    float acc[16][4];
#pragma unroll
    for (int i = 0; i < 16; i++)
#pragma unroll
        for (int j = 0; j < 4; j++) acc[i][j] = 0.0f;

    const uint32_t arow_off =
        (uint32_t)((wm * 64 + (lane & 15)) * 80 + (lane >> 4) * 16);
    const uint32_t brow_off =
        (uint32_t)((wn * 32 + (lane & 7) + ((lane >> 4) & 1) * 8) * 80 +
                   ((lane >> 3) & 1) * 16);

    auto load = [&](int buf, int k0) {
        uint32_t dst = sb + buf * BUF_B;
#pragma unroll
        for (int t = 0; t < 4; t++) {
            const __nv_bfloat16* s = srcs[t] + k0 + cb * 8;
#pragma unroll
            for (int j = 0; j < 2; j++) {
                int r = (tid >> 2) + j * 64;
                cp16(dst + t * TILE_B + r * 80 + cb * 16, s + (size_t)r * ldk);
            }
        }
        asm volatile("cp.async.commit_group;" ::: "memory");
    };

    const int nch = K >> 5;
    load(0, 0);
    for (int i = 0; i < nch; i++) {
        int b = i & 1;
        if (i + 1 < nch) {
            load(b ^ 1, (i + 1) << 5);
            asm volatile("cp.async.wait_group 1;" ::: "memory");
        } else {
            asm volatile("cp.async.wait_group 0;" ::: "memory");
        }
        __syncthreads();
        uint32_t base = sb + b * BUF_B;
        compute_chunk(base, base + TILE_B, base + 2 * TILE_B, base + 3 * TILE_B,
                      arow_off, brow_off, acc);
        __syncthreads();
    }

    const int g = lane >> 2, t4 = lane & 3;
#pragma unroll
    for (int mi = 0; mi < 4; mi++)
#pragma unroll
        for (int ni = 0; ni < 4; ni++) {
            float* c = acc[mi * 4 + ni];
            int r0 = m0 + wm * 64 + mi * 16 + g;
            int col = n0 + wn * 32 + ni * 8 + t4 * 2;
            epi(r0, col, c[0], c[1]);
            epi(r0 + 8, col, c[2], c[3]);
        }
}

// ---------------- epilogues ----------------
struct EpiBias {  // xproj = C + phi_bias
    float* C;
    const float* bias;
    __device__ void operator()(int r, int c, float x, float y) const {
        float2 b = *reinterpret_cast<const float2*>(&bias[c]);
        float2 o = make_float2(x + b.x, y + b.y);
        *reinterpret_cast<float2*>(&C[(size_t)r * DOUT + c]) = o;
    }
};
struct EpiStore {  // raw store (residual GEMM -> g_acc2)
    float* C;
    __device__ void operator()(int r, int c, float x, float y) const {
        *reinterpret_cast<float2*>(&C[(size_t)r * DOUT + c]) = make_float2(x, y);
    }
};
struct EpiOut {  // full stage-B nonlinear epilogue, writes out [n][p][e]
    const float* acc2;    // pre-offset by expert
    const float* bias2p;  // pre-offset
    const float* obiasp;  // pre-offset
    float g2;
    float* out;
    int p;
    __device__ void operator()(int r, int c, float x, float y) const {
        float2 a2 = *reinterpret_cast<const float2*>(&acc2[(size_t)r * DOUT + c]);
        float2 b2 = *reinterpret_cast<const float2*>(&bias2p[c]);
        float2 ob = *reinterpret_cast<const float2*>(&obiasp[c]);
        float o0 = sp_f(sp_f((x + b2.x) * g2) + a2.x) + ob.x;
        float o1 = sp_f(sp_f((y + b2.y) * g2) + a2.y) + ob.y;
        *reinterpret_cast<float2*>(&out[(size_t)r * (PNUM * DOUT) + p * DOUT + c]) =
            make_float2(o0, o1);
    }
};

// ---------------- GEMM kernels ----------------
__global__ __launch_bounds__(256) void gemmA_mma(const float* __restrict__ phi_bias) {
    EpiBias epi{g_xproj, phi_bias};
    gemm_core(g_phi_h, g_phi_l, g_wphi_h, g_wphi_l, QDIM, QDIM,
              blockIdx.y * 128, blockIdx.x * 128, epi);
}

__global__ __launch_bounds__(256) void stageB2_mma() {  // residual: x @ zwT^T -> acc2
    int p = blockIdx.z;
    size_t bo = (size_t)p * DIN * DOUT;
    EpiStore epi{g_acc2 + (size_t)p * N_TOK * DOUT};
    gemm_core(g_x_h, g_x_l, g_zwT_h + bo, g_zwT_l + bo, DIN, DIN,
              blockIdx.y * 128, blockIdx.x * 128, epi);
}

__global__ __launch_bounds__(256) void stageB1_mma(const float* __restrict__ bias2,
                                                   const float* __restrict__ graw2,
                                                   const float* __restrict__ obias,
                                                   float* __restrict__ out) {
    int p = blockIdx.z;
    size_t ao = (size_t)p * N_TOK * DOUT;
    size_t wo = (size_t)p * DOUT * DOUT;
    EpiOut epi{g_acc2 + ao, bias2 + p * DOUT, obias + p * DOUT,
               sig_f(graw2[p]), out, p};
    gemm_core(g_z0_h + ao, g_z0_l + ao, g_w2_h + wo, g_w2_l + wo, DOUT, DOUT,
              blockIdx.y * 128, blockIdx.x * 128, epi);
}

// ---------------- launch ----------------
extern "C" void kernel_launch(void* const* d_in, const int* in_sizes, int n_in,
                              void* d_out, int out_size) {
    const float* x        = (const float*)d_in[0];
    const float* phi_raw  = (const float*)d_in[1];
    const float* phi_bias = (const float*)d_in[2];
    const float* rw2      = (const float*)d_in[3];
    const float* bias2    = (const float*)d_in[4];
    const float* graw2    = (const float*)d_in[5];
    const float* zw       = (const float*)d_in[6];
    const float* graw     = (const float*)d_in[7];
    const float* obias    = (const float*)d_in[8];
    float* out = (float*)d_out;

    cudaFuncSetAttribute(gemmA_mma,  cudaFuncAttributeMaxDynamicSharedMemorySize, GEMM_SMEM);
    cudaFuncSetAttribute(stageB2_mma, cudaFuncAttributeMaxDynamicSharedMemorySize, GEMM_SMEM);
    cudaFuncSetAttribute(stageB1_mma, cudaFuncAttributeMaxDynamicSharedMemorySize, GEMM_SMEM);

    prep_kernel<<<8192, 256>>>(phi_raw, rw2, zw);
    phi_kernel<<<8192, 256>>>(x);
    gemmA_mma<<<dim3(4, 32), 256, GEMM_SMEM>>>(phi_bias);
    z0_kernel<<<16384, 256>>>(graw);
    stageB2_mma<<<dim3(4, 32, 8), 256, GEMM_SMEM>>>();
    stageB1_mma<<<dim3(4, 32, 8), 256, GEMM_SMEM>>>(bias2, graw2, obias, out);
}